// round 12
// baseline (speedup 1.0000x reference)
#include <cuda_runtime.h>
#include <cuda_bf16.h>
#include <math.h>
#include <stdint.h>

#define NB 8
#define NL 4096
#define NH 512
#define NC 64
#define NA 512
#define NM (NB*NL)

// scratch (no allocations allowed -> __device__ globals)
__device__ int   g_sel;
__device__ int   g_cnt[NM];
__device__ unsigned char g_mask[NM];
__device__ int   g_maxci[NB];
__device__ float g_base[NM];
__device__ float g_partials[8][NB][NC][NH];
__device__ float g_ctx[NB][NC][NH];
__device__ int   g_hasany[NB*NC];
__device__ float g_wscratch[(size_t)NB*NC*NL];
__device__ float g_actT[(size_t)NB*NC*NL];                       // activity transposed [b][c][l]
__device__ __align__(16) __nv_bfloat16 g_wptb[(size_t)NA*NH];    // W transposed bf16 [n][k]
__device__ __align__(16) __nv_bfloat16 g_hsb[(size_t)NM*NH];     // hidden bf16 [m][k]

__device__ __forceinline__ uint32_t f2tf32(float x) {
    uint32_t r; asm("cvt.rna.tf32.f32 %0, %1;" : "=r"(r) : "f"(x)); return r;
}
__device__ __forceinline__ uint32_t pk2(float lo, float hi) {
    uint32_t r; asm("cvt.rn.bf16x2.f32 %0, %1, %2;" : "=r"(r) : "f"(hi), "f"(lo)); return r;
}
__device__ __forceinline__ float tanh_ap(float x) {
    float y; asm("tanh.approx.f32 %0, %1;" : "=f"(y) : "f"(x)); return y;
}
__device__ __forceinline__ void mma_tf32(float c[4], uint32_t a0, uint32_t a1,
                                         uint32_t a2, uint32_t a3,
                                         uint32_t b0, uint32_t b1) {
    asm volatile("mma.sync.aligned.m16n8k8.row.col.f32.tf32.tf32.f32 "
                 "{%0,%1,%2,%3}, {%4,%5,%6,%7}, {%8,%9}, {%0,%1,%2,%3};\n"
                 : "+f"(c[0]), "+f"(c[1]), "+f"(c[2]), "+f"(c[3])
                 : "r"(a0), "r"(a1), "r"(a2), "r"(a3), "r"(b0), "r"(b1));
}
__device__ __forceinline__ void mma_bf16(float c[4], uint32_t a0, uint32_t a1,
                                         uint32_t a2, uint32_t a3,
                                         uint32_t b0, uint32_t b1) {
    asm volatile("mma.sync.aligned.m16n8k16.row.col.f32.bf16.bf16.f32 "
                 "{%0,%1,%2,%3}, {%4,%5,%6,%7}, {%8,%9}, {%0,%1,%2,%3};\n"
                 : "+f"(c[0]), "+f"(c[1]), "+f"(c[2]), "+f"(c[3])
                 : "r"(a0), "r"(a1), "r"(a2), "r"(a3), "r"(b0), "r"(b1));
}
__device__ __forceinline__ void ldsm_x4(uint32_t& r0, uint32_t& r1, uint32_t& r2,
                                        uint32_t& r3, uint32_t addr) {
    asm volatile("ldmatrix.sync.aligned.m8n8.x4.shared.b16 {%0,%1,%2,%3}, [%4];"
                 : "=r"(r0), "=r"(r1), "=r"(r2), "=r"(r3) : "r"(addr));
}
__device__ __forceinline__ void cp16(uint32_t dst, const void* src) {
    asm volatile("cp.async.cg.shared.global [%0], [%1], 16;" :: "r"(dst), "l"(src));
}
__device__ __forceinline__ uint32_t smem_u32(const void* p) {
    uint32_t a;
    asm("{ .reg .u64 t; cvta.to.shared.u64 t, %1; cvt.u32.u64 %0, t; }" : "=r"(a) : "l"(p));
    return a;
}

// ----------------------------------------------------------------------------
// Kernel 0: classify ambiguous input pairs + init maxci.
// ----------------------------------------------------------------------------
__global__ void k_classify(const unsigned int* __restrict__ a, const unsigned int* __restrict__ b,
                           const float* __restrict__ f0, const float* __restrict__ f1) {
    __shared__ unsigned int ra[256], rb[256];
    __shared__ float fa[256];
    const int tid = threadIdx.x;
    if (tid < NB) g_maxci[tid] = 1;
    unsigned int ma = 0, mb = 0;
    for (int i = tid; i < 8192; i += 256) {
        ma = max(ma, a[i]);
        mb = max(mb, b[i]);
    }
    float f0m = 0.f;
    for (int i = tid; i < 512; i += 256) f0m = fmaxf(f0m, fabsf(f0[i]));
    (void)f1;
    ra[tid] = ma; rb[tid] = mb; fa[tid] = f0m;
    __syncthreads();
    for (int s = 128; s > 0; s >>= 1) {
        if (tid < s) {
            ra[tid] = max(ra[tid], ra[tid + s]);
            rb[tid] = max(rb[tid], rb[tid + s]);
            fa[tid] = fmaxf(fa[tid], fa[tid + s]);
        }
        __syncthreads();
    }
    if (tid == 0) {
        int sel = 0;
        bool a_is_count = (ra[0] >= 2u && ra[0] < 64u);
        if (a_is_count) sel |= 1;
        unsigned int mmax = a_is_count ? rb[0] : ra[0];
        if (mmax >= 256u) sel |= 2;
        if (fa[0] < 1e-30f) sel |= 4;
        g_sel = sel;
    }
}

// ----------------------------------------------------------------------------
// Kernel 0f: FUSED preprocessing (cvth / acttr / cvtw / prep by block range)
// ----------------------------------------------------------------------------
#define PREP_BLOCKS 10496
__global__ void k_prepall(const float* __restrict__ Hs, const float* __restrict__ act,
                          const float* __restrict__ Wp,
                          const void* __restrict__ c0, const void* __restrict__ c1) {
    __shared__ float t[32][33];
    __shared__ int sm[256];
    const int tid = threadIdx.x;
    int bid = blockIdx.x;

    if (bid < 8192) {                       // ---- cvth ----
        size_t i = ((size_t)bid * 256 + tid) * 8;
        float4 a = *reinterpret_cast<const float4*>(&Hs[i]);
        float4 b = *reinterpret_cast<const float4*>(&Hs[i + 4]);
        uint4 u;
        u.x = pk2(a.x, a.y); u.y = pk2(a.z, a.w);
        u.z = pk2(b.x, b.y); u.w = pk2(b.z, b.w);
        *reinterpret_cast<uint4*>(&g_hsb[i]) = u;
        return;
    }
    bid -= 8192;
    if (bid < 2048) {                       // ---- acttr ----
        const int l0 = (bid & 127) * 32;
        const int c0i = ((bid >> 7) & 1) * 32;
        const int b  = bid >> 8;
        const int x = tid & 31, y = tid >> 5;   // 32 x 8
        #pragma unroll
        for (int i = y; i < 32; i += 8)
            t[i][x] = act[((size_t)(b * NL + l0 + i)) * NC + c0i + x];
        __syncthreads();
        #pragma unroll
        for (int i = y; i < 32; i += 8)
            g_actT[((size_t)(b * NC + c0i + i)) * NL + l0 + x] = t[x][i];
        return;
    }
    bid -= 2048;
    if (bid < 128) {                        // ---- cvtw ----
        const int idx = bid * 256 + tid;
        const int n = idx & 511;
        const int k0 = (idx >> 9) * 8;
        float v[8];
        #pragma unroll
        for (int j = 0; j < 8; j++) v[j] = Wp[(size_t)(k0 + j) * NA + n];
        uint4 u;
        u.x = pk2(v[0], v[1]); u.y = pk2(v[2], v[3]);
        u.z = pk2(v[4], v[5]); u.w = pk2(v[6], v[7]);
        *reinterpret_cast<uint4*>(&g_wptb[(size_t)n * NH + k0]) = u;
        return;
    }
    bid -= 128;
    {                                       // ---- prep ---- (128 blocks)
        const int i = bid * 256 + tid;
        const int sel = g_sel;
        const int* cntp   = (const int*)((sel & 1) ? c0 : c1);
        const void* maskp = (sel & 1) ? c1 : c0;
        int cv = cntp[i];
        g_cnt[i] = cv;
        unsigned char mv;
        if (sel & 2) mv = (((const unsigned char*)maskp)[i] != 0) ? 1 : 0;
        else         mv = (((const int*)maskp)[i] != 0) ? 1 : 0;
        g_mask[i] = mv;
        sm[tid] = cv; __syncthreads();
        for (int s = 128; s > 0; s >>= 1) {
            if (tid < s) sm[tid] = max(sm[tid], sm[tid + s]);
            __syncthreads();
        }
        if (tid == 0) atomicMax(&g_maxci[bid >> 4], sm[0]);
    }
}

// ----------------------------------------------------------------------------
// Kernel 1: fused logits. bf16 mma.sync + ldmatrix + 4-stage cp.async pipeline.
// BM=128, BN=128, BK=32; 8 warps (2x4); warp tile 64x32.
// ----------------------------------------------------------------------------
#define ST_BYTES 10240
#define N_STAGE 4
#define LOG_SMEM (2 * N_STAGE * ST_BYTES)

__global__ void __launch_bounds__(256, 2)
k_logits(const float* __restrict__ v0, const float* __restrict__ v1,
         const float* __restrict__ sb) {
    extern __shared__ __align__(16) char dsm[];
    __shared__ float red[4][128];
    __shared__ float pbs[NA], sws[NA];
    const int sel = g_sel;
    const float* pb = (sel & 4) ? v0 : v1;
    const float* sw = (sel & 4) ? v1 : v0;
    const int m0  = blockIdx.x * 128;
    const int tid = threadIdx.x;
    const int wid = tid >> 5, lane = tid & 31;
    const int wm = wid & 1, wn = wid >> 1;
    const int lk = lane & 3, lg = lane >> 2;

    // stage pb/sw into smem once
    {
        int i = tid;
        pbs[i] = pb[i]; sws[i] = sw[i];
        pbs[i + 256] = pb[i + 256]; sws[i + 256] = sw[i + 256];
    }

    const int cr = tid >> 2;
    const int cc = tid & 3;
    const __nv_bfloat16* Ag = g_hsb + (size_t)m0 * NH;

    const uint32_t sbase = smem_u32(dsm);

    const int a_row = wm * 64 + (lane & 7) + ((lane >> 3) & 1) * 8;
    const int a_kb  = (lane >> 4) * 16;
    const int b_row = wn * 32 + (lane >> 4) * 8 + (lane & 7);
    const int b_kb  = ((lane >> 3) & 1) * 16;

    float part[8];
    #pragma unroll
    for (int i = 0; i < 8; i++) part[i] = 0.f;

    for (int n0i = 0; n0i < 4; n0i++) {
        const __nv_bfloat16* Bg = g_wptb + (size_t)(n0i * 128) * NH;
        float acc[4][4][4];
        #pragma unroll
        for (int mt = 0; mt < 4; mt++)
            #pragma unroll
            for (int nt = 0; nt < 4; nt++)
                #pragma unroll
                for (int q = 0; q < 4; q++) acc[mt][nt][q] = 0.f;

        // prologue: prefetch slabs 0..2 into stages 0..2
        #pragma unroll
        for (int p = 0; p < N_STAGE - 1; p++) {
            const uint32_t aoff = sbase + p * ST_BYTES;
            const uint32_t boff = sbase + N_STAGE * ST_BYTES + p * ST_BYTES;
            #pragma unroll
            for (int it = 0; it < 2; it++) {
                int r = cr + it * 64;
                cp16(aoff + r * 80 + cc * 16, Ag + (size_t)r * NH + p * 32 + cc * 8);
                cp16(boff + r * 80 + cc * 16, Bg + (size_t)r * NH + p * 32 + cc * 8);
            }
            asm volatile("cp.async.commit_group;");
        }

        for (int s = 0; s < 16; s++) {
            const int st = s % N_STAGE;
            if (s < 16 - (N_STAGE - 1)) asm volatile("cp.async.wait_group %0;" :: "n"(N_STAGE - 2));
            else                        asm volatile("cp.async.wait_group 0;");
            __syncthreads();

            if (s + N_STAGE - 1 < 16) {
                const int pst = (s + N_STAGE - 1) % N_STAGE;
                const int k0 = (s + N_STAGE - 1) * 32;
                const uint32_t aoff = sbase + pst * ST_BYTES;
                const uint32_t boff = sbase + N_STAGE * ST_BYTES + pst * ST_BYTES;
                #pragma unroll
                for (int it = 0; it < 2; it++) {
                    int r = cr + it * 64;
                    cp16(aoff + r * 80 + cc * 16, Ag + (size_t)r * NH + k0 + cc * 8);
                    cp16(boff + r * 80 + cc * 16, Bg + (size_t)r * NH + k0 + cc * 8);
                }
                asm volatile("cp.async.commit_group;");
            }

            const uint32_t abase = sbase + st * ST_BYTES + a_row * 80 + a_kb;
            const uint32_t bbase = sbase + N_STAGE * ST_BYTES + st * ST_BYTES + b_row * 80 + b_kb;
            #pragma unroll
            for (int ks = 0; ks < 2; ks++) {
                uint32_t af[4][4], bfr[2][4];
                #pragma unroll
                for (int mt = 0; mt < 4; mt++)
                    ldsm_x4(af[mt][0], af[mt][1], af[mt][2], af[mt][3],
                            abase + mt * 16 * 80 + ks * 32);
                #pragma unroll
                for (int np = 0; np < 2; np++)
                    ldsm_x4(bfr[np][0], bfr[np][1], bfr[np][2], bfr[np][3],
                            bbase + np * 16 * 80 + ks * 32);
                #pragma unroll
                for (int mt = 0; mt < 4; mt++)
                    #pragma unroll
                    for (int nt = 0; nt < 4; nt++)
                        mma_bf16(acc[mt][nt], af[mt][0], af[mt][1], af[mt][2], af[mt][3],
                                 bfr[nt >> 1][(nt & 1) * 2], bfr[nt >> 1][(nt & 1) * 2 + 1]);
            }
        }
        __syncthreads();

        // fused epilogue: tanh.approx + dot with score weights (smem pb/sw)
        #pragma unroll
        for (int nt = 0; nt < 4; nt++) {
            int n = n0i * 128 + wn * 32 + nt * 8 + 2 * lk;
            float pv0 = pbs[n], pv1 = pbs[n + 1];
            float sv0 = sws[n], sv1 = sws[n + 1];
            #pragma unroll
            for (int mt = 0; mt < 4; mt++) {
                part[mt*2+0] += tanh_ap(acc[mt][nt][0] + pv0) * sv0
                              + tanh_ap(acc[mt][nt][1] + pv1) * sv1;
                part[mt*2+1] += tanh_ap(acc[mt][nt][2] + pv0) * sv0
                              + tanh_ap(acc[mt][nt][3] + pv1) * sv1;
            }
        }
    }
    #pragma unroll
    for (int off = 1; off < 4; off <<= 1)
        #pragma unroll
        for (int i = 0; i < 8; i++)
            part[i] += __shfl_xor_sync(0xffffffffu, part[i], off);
    if (lk == 0) {
        #pragma unroll
        for (int mt = 0; mt < 4; mt++) {
            red[wn][wm * 64 + mt * 16 + lg    ] = part[mt*2+0];
            red[wn][wm * 64 + mt * 16 + lg + 8] = part[mt*2+1];
        }
    }
    __syncthreads();
    if (tid < 128) {
        int m = m0 + tid;
        float s = red[0][tid] + red[1][tid] + red[2][tid] + red[3][tid];
        float cf = fmaxf((float)g_cnt[m], 0.f);
        g_base[m] = s + sb[0] + log1pf(cf);
    }
}

// ----------------------------------------------------------------------------
// Kernel 3: per-(b,c) masked softmax — 1024 threads, register-resident.
// ----------------------------------------------------------------------------
__global__ void __launch_bounds__(1024)
k_softmax(float* __restrict__ wout) {
    __shared__ float red[32];
    __shared__ float bcast;
    const int bc = blockIdx.x;
    const int b = bc / NC;
    const int tid = threadIdx.x;
    const int lane = tid & 31, wrp = tid >> 5;

    float4 a = *reinterpret_cast<const float4*>(&g_actT[(size_t)bc * NL + tid * 4]);
    float4 bb = *reinterpret_cast<const float4*>(&g_base[b * NL + tid * 4]);
    float v[4];
    v[0] = (a.x > 0.f) ? (bb.x + __logf(1.f + a.x)) : -INFINITY;
    v[1] = (a.y > 0.f) ? (bb.y + __logf(1.f + a.y)) : -INFINITY;
    v[2] = (a.z > 0.f) ? (bb.z + __logf(1.f + a.z)) : -INFINITY;
    v[3] = (a.w > 0.f) ? (bb.w + __logf(1.f + a.w)) : -INFINITY;

    float m = fmaxf(fmaxf(v[0], v[1]), fmaxf(v[2], v[3]));
    #pragma unroll
    for (int off = 16; off > 0; off >>= 1)
        m = fmaxf(m, __shfl_xor_sync(0xffffffffu, m, off));
    if (lane == 0) red[wrp] = m;
    __syncthreads();
    if (wrp == 0) {
        float t = red[lane];
        #pragma unroll
        for (int off = 16; off > 0; off >>= 1)
            t = fmaxf(t, __shfl_xor_sync(0xffffffffu, t, off));
        if (lane == 0) bcast = t;
    }
    __syncthreads();
    float bmax = bcast;

    float4* wrow4 = reinterpret_cast<float4*>(wout + (size_t)bc * NL);
    if (bmax == -INFINITY) {
        wrow4[tid] = make_float4(0.f, 0.f, 0.f, 0.f);
        if (tid == 0) g_hasany[bc] = 0;
        return;
    }
    float e[4];
    #pragma unroll
    for (int i = 0; i < 4; i++) {
        float d = v[i] - bmax;
        e[i] = (d < -87.f) ? 0.f : __expf(d);
    }
    float s = (e[0] + e[1]) + (e[2] + e[3]);
    #pragma unroll
    for (int off = 16; off > 0; off >>= 1)
        s += __shfl_xor_sync(0xffffffffu, s, off);
    if (lane == 0) red[wrp] = s;
    __syncthreads();
    if (wrp == 0) {
        float t = red[lane];
        #pragma unroll
        for (int off = 16; off > 0; off >>= 1)
            t += __shfl_xor_sync(0xffffffffu, t, off);
        if (lane == 0) bcast = t;
    }
    __syncthreads();
    float inv = 1.f / bcast;
    wrow4[tid] = make_float4(e[0] * inv, e[1] * inv, e[2] * inv, e[3] * inv);
    if (tid == 0) g_hasany[bc] = 1;
}

// ----------------------------------------------------------------------------
// Kernel 4: ctx partials via tf32 MMA, natural-layout tiles + 4-stage cp.async.
// ----------------------------------------------------------------------------
#define CA_ST 5120
#define CB_ST 8704
__global__ void __launch_bounds__(256)
k_ctx_partial(const float* __restrict__ w, const float* __restrict__ Hs) {
    __shared__ __align__(16) float As[4][64 * 20];
    __shared__ __align__(16) float Bs[4][16 * 136];
    const int h0 = blockIdx.x * 128;
    const int l0 = blockIdx.y * 512;
    const int b  = blockIdx.z;
    const int tid = threadIdx.x;
    const int wid = tid >> 5, lane = tid & 31;
    const int wm = wid & 1, wn = wid >> 1;
    const int lk = lane & 3, lg = lane >> 2;

    const uint32_t asb = smem_u32(&As[0][0]);
    const uint32_t bsb = smem_u32(&Bs[0][0]);
    const int ar = tid >> 2, ac = tid & 3;
    const float* wbase = w + (size_t)(b * NC) * NL + l0;
    const float* hbase = Hs + ((size_t)(b * NL + l0)) * NH + h0;

    float acc[2][4][4];
    #pragma unroll
    for (int mt = 0; mt < 2; mt++)
        #pragma unroll
        for (int nt = 0; nt < 4; nt++)
            #pragma unroll
            for (int q = 0; q < 4; q++) acc[mt][nt][q] = 0.f;

    #pragma unroll
    for (int p = 0; p < 3; p++) {
        cp16(asb + p * CA_ST + ar * 80 + ac * 16, wbase + (size_t)ar * NL + p * 16 + ac * 4);
        #pragma unroll
        for (int i = 0; i < 2; i++) {
            int idx = tid + i * 256;
            int r = idx >> 5, ch = idx & 31;
            cp16(bsb + p * CB_ST + r * 544 + ch * 16, hbase + (size_t)(p * 16 + r) * NH + ch * 4);
        }
        asm volatile("cp.async.commit_group;");
    }

    for (int s = 0; s < 32; s++) {
        const int st = s & 3;
        if (s < 29) asm volatile("cp.async.wait_group 2;");
        else        asm volatile("cp.async.wait_group 0;");
        __syncthreads();

        if (s + 3 < 32) {
            const int pst = (s + 3) & 3;
            const int k0 = (s + 3) * 16;
            cp16(asb + pst * CA_ST + ar * 80 + ac * 16, wbase + (size_t)ar * NL + k0 + ac * 4);
            #pragma unroll
            for (int i = 0; i < 2; i++) {
                int idx = tid + i * 256;
                int r = idx >> 5, ch = idx & 31;
                cp16(bsb + pst * CB_ST + r * 544 + ch * 16, hbase + (size_t)(k0 + r) * NH + ch * 4);
            }
            asm volatile("cp.async.commit_group;");
        }

        #pragma unroll
        for (int ks = 0; ks < 2; ks++) {
            const int kb = ks * 8;
            uint32_t af[2][4], bf[4][2];
            #pragma unroll
            for (int mt = 0; mt < 2; mt++) {
                int mb = wm * 32 + mt * 16 + lg;
                af[mt][0] = f2tf32(As[st][(mb    ) * 20 + kb + lk    ]);
                af[mt][1] = f2tf32(As[st][(mb + 8) * 20 + kb + lk    ]);
                af[mt][2] = f2tf32(As[st][(mb    ) * 20 + kb + lk + 4]);
                af[mt][3] = f2tf32(As[st][(mb + 8) * 20 + kb + lk + 4]);
            }
            #pragma unroll
            for (int nt = 0; nt < 4; nt++) {
                int nb = wn * 32 + nt * 8 + lg;
                bf[nt][0] = f2tf32(Bs[st][(kb + lk    ) * 136 + nb]);
                bf[nt][1] = f2tf32(Bs[st][(kb + lk + 4) * 136 + nb]);
            }
            #pragma unroll
            for (int mt = 0; mt < 2; mt++)
                #pragma unroll
                for (int nt = 0; nt < 4; nt++)
                    mma_tf32(acc[mt][nt], af[mt][0], af[mt][1], af[mt][2], af[mt][3],
                             bf[nt][0], bf[nt][1]);
        }
    }
    const int p = blockIdx.y;
    #pragma unroll
    for (int mt = 0; mt < 2; mt++) {
        int c0 = wm * 32 + mt * 16 + lg;
        #pragma unroll
        for (int nt = 0; nt < 4; nt++) {
            int h = h0 + wn * 32 + nt * 8 + 2 * lk;
            *reinterpret_cast<float2*>(&g_partials[p][b][c0    ][h]) =
                make_float2(acc[mt][nt][0], acc[mt][nt][1]);
            *reinterpret_cast<float2*>(&g_partials[p][b][c0 + 8][h]) =
                make_float2(acc[mt][nt][2], acc[mt][nt][3]);
        }
    }
}

// ----------------------------------------------------------------------------
// Kernel 5: finalize contexts
// ----------------------------------------------------------------------------
__global__ void k_ctx_final(const float* __restrict__ Hs) {
    int idx = blockIdx.x * 256 + threadIdx.x;
    int h = idx & (NH - 1);
    int c = (idx >> 9) & (NC - 1);
    int b = idx >> 15;
    if (g_hasany[b * NC + c]) {
        float s = 0.f;
        #pragma unroll
        for (int p = 0; p < 8; p++) s += g_partials[p][b][c][h];
        g_ctx[b][c][h] = s;
    } else {
        g_ctx[b][c][h] = Hs[((size_t)(b * NL + (NL - 1))) * NH + h];
    }
}

// ----------------------------------------------------------------------------
// Kernel 6: expanded = mix @ contexts via tf32 MMA, then gate/select.
// ----------------------------------------------------------------------------
__global__ void __launch_bounds__(256)
k_expand(const float* __restrict__ act, const float* __restrict__ Hs,
         float* __restrict__ out) {
    __shared__ float mixs[64][72];
    __shared__ float ctxs[64][72];
    __shared__ float rs[64];
    const int h0 = blockIdx.x * 64;
    const int l0 = blockIdx.y * 64;
    const int b  = blockIdx.z;
    const int tid = threadIdx.x;
    const int wid = tid >> 5, lane = tid & 31;
    const int wm = wid & 1, wn = wid >> 1;
    const int lk = lane & 3, lg = lane >> 2;

    #pragma unroll
    for (int it = 0; it < 4; it++) {
        int idx = tid + it * 256;
        int l = idx >> 4, q = idx & 15;
        float4 v = *reinterpret_cast<const float4*>(
            &act[((size_t)(b * NL + l0 + l)) * NC + q * 4]);
        mixs[q*4+0][l] = fmaxf(v.x, 0.f);
        mixs[q*4+1][l] = fmaxf(v.y, 0.f);
        mixs[q*4+2][l] = fmaxf(v.z, 0.f);
        mixs[q*4+3][l] = fmaxf(v.w, 0.f);
    }
    #pragma unroll
    for (int it = 0; it < 4; it++) {
        int idx = tid + it * 256;
        int c = idx >> 4, q = idx & 15;
        float4 v = *reinterpret_cast<const float4*>(&g_ctx[b][c][h0 + q * 4]);
        *reinterpret_cast<float4*>(&ctxs[c][q*4]) = v;
    }
    __syncthreads();
    if (tid < 64) {
        float s = 0.f;
        #pragma unroll
        for (int c = 0; c < 64; c++) s += mixs[c][tid];
        rs[tid] = 1.f / fmaxf(s, 1.f);
    }
    __syncthreads();
    #pragma unroll
    for (int it = 0; it < 16; it++) {
        int idx = tid + it * 256;
        int c = idx >> 6, l = idx & 63;
        mixs[c][l] *= rs[l];
    }
    __syncthreads();

    float acc[2][2][4];
    #pragma unroll
    for (int mt = 0; mt < 2; mt++)
        #pragma unroll
        for (int nt = 0; nt < 2; nt++)
            #pragma unroll
            for (int q = 0; q < 4; q++) acc[mt][nt][q] = 0.f;

    #pragma unroll
    for (int ks = 0; ks < 8; ks++) {
        const int kb = ks * 8;
        uint32_t af[2][4], bf[2][2];
        #pragma unroll
        for (int mt = 0; mt < 2; mt++) {
            int mb = wm * 32 + mt * 16 + lg;
            af[mt][0] = f2tf32(mixs[kb + lk    ][mb    ]);
            af[mt][1] = f2tf32(mixs[kb + lk    ][mb + 8]);
            af[mt][2] = f2tf32(mixs[kb + lk + 4][mb    ]);
            af[mt][3] = f2tf32(mixs[kb + lk + 4][mb + 8]);
        }
        #pragma unroll
        for (int nt = 0; nt < 2; nt++) {
            int nb = wn * 16 + nt * 8 + lg;
            bf[nt][0] = f2tf32(ctxs[kb + lk    ][nb]);
            bf[nt][1] = f2tf32(ctxs[kb + lk + 4][nb]);
        }
        #pragma unroll
        for (int mt = 0; mt < 2; mt++)
            #pragma unroll
            for (int nt = 0; nt < 2; nt++)
                mma_tf32(acc[mt][nt], af[mt][0], af[mt][1], af[mt][2], af[mt][3],
                         bf[nt][0], bf[nt][1]);
    }

    #pragma unroll
    for (int mt = 0; mt < 2; mt++) {
        #pragma unroll
        for (int half = 0; half < 2; half++) {
            int l = l0 + wm * 32 + mt * 16 + lg + half * 8;
            size_t m = (size_t)b * NL + l;
            bool msk = g_mask[m];
            float gate = 1.f + (float)g_cnt[m] / (float)g_maxci[b];
            #pragma unroll
            for (int nt = 0; nt < 2; nt++) {
                int h = h0 + wn * 16 + nt * 8 + 2 * lk;
                float2 o;
                if (msk) {
                    o = make_float2(acc[mt][nt][half*2+0] * gate,
                                    acc[mt][nt][half*2+1] * gate);
                } else {
                    o = *reinterpret_cast<const float2*>(&Hs[m * NH + h]);
                }
                *reinterpret_cast<float2*>(&out[m * NH + h]) = o;
            }
        }
    }
}

// ----------------------------------------------------------------------------
extern "C" void kernel_launch(void* const* d_in, const int* in_sizes, int n_in,
                              void* d_out, int out_size) {
    const float* hs = nullptr;
    const float* act = nullptr;
    const float* pw = nullptr;
    const float* sb = nullptr;
    const void*  p32k[2] = {nullptr, nullptr}; int n32 = 0;
    const float* p512[2] = {nullptr, nullptr}; int n512 = 0;
    for (int i = 0; i < n_in; i++) {
        long long s = in_sizes[i];
        if      (s == 16777216) hs  = (const float*)d_in[i];
        else if (s == 2097152)  act = (const float*)d_in[i];
        else if (s == 262144)   pw  = (const float*)d_in[i];
        else if (s == 1)        sb  = (const float*)d_in[i];
        else if (s == 32768 && n32 < 2)  p32k[n32++] = d_in[i];
        else if (s == 512   && n512 < 2) p512[n512++] = (const float*)d_in[i];
    }

    float* out = (float*)d_out;
    const size_t attended_elems = (size_t)NB * NL * NH;
    const size_t weights_elems  = (size_t)NB * NC * NL;
    float* wout;
    if ((size_t)out_size >= attended_elems + weights_elems) {
        wout = out + attended_elems;
    } else {
        cudaGetSymbolAddress((void**)&wout, g_wscratch);
    }

    cudaFuncSetAttribute(k_logits, cudaFuncAttributeMaxDynamicSharedMemorySize, LOG_SMEM);

    k_classify   <<< 1, 256 >>>((const unsigned int*)p32k[0], (const unsigned int*)p32k[1],
                                p512[0], p512[1]);
    k_prepall    <<< PREP_BLOCKS, 256 >>>(hs, act, pw, p32k[0], p32k[1]);
    k_logits     <<< NM / 128, 256, LOG_SMEM >>>(p512[0], p512[1], sb);
    k_softmax    <<< NB * NC, 1024 >>>(wout);
    k_ctx_partial<<< dim3(NH / 128, 8, NB), 256 >>>(wout, hs);
    k_ctx_final  <<< (NB * NC * NH) / 256, 256 >>>(hs);
    k_expand     <<< dim3(NH / 64, NL / 64, NB), 256 >>>(act, hs, out);
}

// round 13
// speedup vs baseline: 1.0678x; 1.0678x over previous
#include <cuda_runtime.h>
#include <cuda_bf16.h>
#include <math.h>
#include <stdint.h>

#define NB 8
#define NL 4096
#define NH 512
#define NC 64
#define NA 512
#define NM (NB*NL)

// scratch (no allocations allowed -> __device__ globals)
__device__ int   g_sel;
__device__ int   g_cnt[NM];
__device__ unsigned char g_mask[NM];
__device__ int   g_maxci[NB];
__device__ float g_base[NM];
__device__ float g_partials[8][NB][NC][NH];
__device__ float g_ctx[NB][NC][NH];
__device__ int   g_hasany[NB*NC];
__device__ float g_wscratch[(size_t)NB*NC*NL];
__device__ float g_actT[(size_t)NB*NC*NL];                       // activity transposed [b][c][l]
__device__ __align__(16) __nv_bfloat16 g_wptb[(size_t)NA*NH];    // W transposed bf16 [n][k]
__device__ __align__(16) __nv_bfloat16 g_hsb[(size_t)NM*NH];     // hidden bf16 [m][k]

__device__ __forceinline__ uint32_t f2tf32(float x) {
    uint32_t r; asm("cvt.rna.tf32.f32 %0, %1;" : "=r"(r) : "f"(x)); return r;
}
__device__ __forceinline__ uint32_t pk2(float lo, float hi) {
    uint32_t r; asm("cvt.rn.bf16x2.f32 %0, %1, %2;" : "=r"(r) : "f"(hi), "f"(lo)); return r;
}
__device__ __forceinline__ float tanh_ap(float x) {
    float y; asm("tanh.approx.f32 %0, %1;" : "=f"(y) : "f"(x)); return y;
}
__device__ __forceinline__ void mma_tf32(float c[4], uint32_t a0, uint32_t a1,
                                         uint32_t a2, uint32_t a3,
                                         uint32_t b0, uint32_t b1) {
    asm volatile("mma.sync.aligned.m16n8k8.row.col.f32.tf32.tf32.f32 "
                 "{%0,%1,%2,%3}, {%4,%5,%6,%7}, {%8,%9}, {%0,%1,%2,%3};\n"
                 : "+f"(c[0]), "+f"(c[1]), "+f"(c[2]), "+f"(c[3])
                 : "r"(a0), "r"(a1), "r"(a2), "r"(a3), "r"(b0), "r"(b1));
}
__device__ __forceinline__ void mma_bf16(float c[4], uint32_t a0, uint32_t a1,
                                         uint32_t a2, uint32_t a3,
                                         uint32_t b0, uint32_t b1) {
    asm volatile("mma.sync.aligned.m16n8k16.row.col.f32.bf16.bf16.f32 "
                 "{%0,%1,%2,%3}, {%4,%5,%6,%7}, {%8,%9}, {%0,%1,%2,%3};\n"
                 : "+f"(c[0]), "+f"(c[1]), "+f"(c[2]), "+f"(c[3])
                 : "r"(a0), "r"(a1), "r"(a2), "r"(a3), "r"(b0), "r"(b1));
}
__device__ __forceinline__ void ldsm_x4(uint32_t& r0, uint32_t& r1, uint32_t& r2,
                                        uint32_t& r3, uint32_t addr) {
    asm volatile("ldmatrix.sync.aligned.m8n8.x4.shared.b16 {%0,%1,%2,%3}, [%4];"
                 : "=r"(r0), "=r"(r1), "=r"(r2), "=r"(r3) : "r"(addr));
}
__device__ __forceinline__ void cp16(uint32_t dst, const void* src) {
    asm volatile("cp.async.cg.shared.global [%0], [%1], 16;" :: "r"(dst), "l"(src));
}
__device__ __forceinline__ uint32_t smem_u32(const void* p) {
    uint32_t a;
    asm("{ .reg .u64 t; cvta.to.shared.u64 t, %1; cvt.u32.u64 %0, t; }" : "=r"(a) : "l"(p));
    return a;
}

// ----------------------------------------------------------------------------
// Kernel 0: classify ambiguous input pairs + init maxci.
// ----------------------------------------------------------------------------
__global__ void k_classify(const unsigned int* __restrict__ a, const unsigned int* __restrict__ b,
                           const float* __restrict__ f0, const float* __restrict__ f1) {
    __shared__ unsigned int ra[256], rb[256];
    __shared__ float fa[256];
    const int tid = threadIdx.x;
    if (tid < NB) g_maxci[tid] = 1;
    unsigned int ma = 0, mb = 0;
    for (int i = tid; i < 8192; i += 256) {
        ma = max(ma, a[i]);
        mb = max(mb, b[i]);
    }
    float f0m = 0.f;
    for (int i = tid; i < 512; i += 256) f0m = fmaxf(f0m, fabsf(f0[i]));
    (void)f1;
    ra[tid] = ma; rb[tid] = mb; fa[tid] = f0m;
    __syncthreads();
    for (int s = 128; s > 0; s >>= 1) {
        if (tid < s) {
            ra[tid] = max(ra[tid], ra[tid + s]);
            rb[tid] = max(rb[tid], rb[tid + s]);
            fa[tid] = fmaxf(fa[tid], fa[tid + s]);
        }
        __syncthreads();
    }
    if (tid == 0) {
        int sel = 0;
        bool a_is_count = (ra[0] >= 2u && ra[0] < 64u);
        if (a_is_count) sel |= 1;
        unsigned int mmax = a_is_count ? rb[0] : ra[0];
        if (mmax >= 256u) sel |= 2;
        if (fa[0] < 1e-30f) sel |= 4;
        g_sel = sel;
    }
}

// ----------------------------------------------------------------------------
// Kernel 0f: FUSED preprocessing (cvth / acttr / cvtw / prep by block range)
// ----------------------------------------------------------------------------
#define PREP_BLOCKS 10496
__global__ void k_prepall(const float* __restrict__ Hs, const float* __restrict__ act,
                          const float* __restrict__ Wp,
                          const void* __restrict__ c0, const void* __restrict__ c1) {
    __shared__ float t[32][33];
    __shared__ int sm[256];
    const int tid = threadIdx.x;
    int bid = blockIdx.x;

    if (bid < 8192) {                       // ---- cvth ----
        size_t i = ((size_t)bid * 256 + tid) * 8;
        float4 a = *reinterpret_cast<const float4*>(&Hs[i]);
        float4 b = *reinterpret_cast<const float4*>(&Hs[i + 4]);
        uint4 u;
        u.x = pk2(a.x, a.y); u.y = pk2(a.z, a.w);
        u.z = pk2(b.x, b.y); u.w = pk2(b.z, b.w);
        *reinterpret_cast<uint4*>(&g_hsb[i]) = u;
        return;
    }
    bid -= 8192;
    if (bid < 2048) {                       // ---- acttr ----
        const int l0 = (bid & 127) * 32;
        const int c0i = ((bid >> 7) & 1) * 32;
        const int b  = bid >> 8;
        const int x = tid & 31, y = tid >> 5;   // 32 x 8
        #pragma unroll
        for (int i = y; i < 32; i += 8)
            t[i][x] = act[((size_t)(b * NL + l0 + i)) * NC + c0i + x];
        __syncthreads();
        #pragma unroll
        for (int i = y; i < 32; i += 8)
            g_actT[((size_t)(b * NC + c0i + i)) * NL + l0 + x] = t[x][i];
        return;
    }
    bid -= 2048;
    if (bid < 128) {                        // ---- cvtw ----
        const int idx = bid * 256 + tid;
        const int n = idx & 511;
        const int k0 = (idx >> 9) * 8;
        float v[8];
        #pragma unroll
        for (int j = 0; j < 8; j++) v[j] = Wp[(size_t)(k0 + j) * NA + n];
        uint4 u;
        u.x = pk2(v[0], v[1]); u.y = pk2(v[2], v[3]);
        u.z = pk2(v[4], v[5]); u.w = pk2(v[6], v[7]);
        *reinterpret_cast<uint4*>(&g_wptb[(size_t)n * NH + k0]) = u;
        return;
    }
    bid -= 128;
    {                                       // ---- prep ---- (128 blocks)
        const int i = bid * 256 + tid;
        const int sel = g_sel;
        const int* cntp   = (const int*)((sel & 1) ? c0 : c1);
        const void* maskp = (sel & 1) ? c1 : c0;
        int cv = cntp[i];
        g_cnt[i] = cv;
        unsigned char mv;
        if (sel & 2) mv = (((const unsigned char*)maskp)[i] != 0) ? 1 : 0;
        else         mv = (((const int*)maskp)[i] != 0) ? 1 : 0;
        g_mask[i] = mv;
        sm[tid] = cv; __syncthreads();
        for (int s = 128; s > 0; s >>= 1) {
            if (tid < s) sm[tid] = max(sm[tid], sm[tid + s]);
            __syncthreads();
        }
        if (tid == 0) atomicMax(&g_maxci[bid >> 4], sm[0]);
    }
}

// ----------------------------------------------------------------------------
// Kernel 1: fused logits. bf16 mma.sync + ldmatrix + 3-stage cp.async pipeline.
// BM=128, BN=128, BK=32; 8 warps (2x4); warp tile 64x32.  (R11 config)
// ----------------------------------------------------------------------------
#define ST_BYTES 10240
#define LOG_SMEM (6 * ST_BYTES)

__global__ void __launch_bounds__(256, 2)
k_logits(const float* __restrict__ v0, const float* __restrict__ v1,
         const float* __restrict__ sb) {
    extern __shared__ __align__(16) char dsm[];
    __shared__ float red[4][128];
    __shared__ float pbs[NA], sws[NA];
    const int sel = g_sel;
    const float* pb = (sel & 4) ? v0 : v1;
    const float* sw = (sel & 4) ? v1 : v0;
    const int m0  = blockIdx.x * 128;
    const int tid = threadIdx.x;
    const int wid = tid >> 5, lane = tid & 31;
    const int wm = wid & 1, wn = wid >> 1;
    const int lk = lane & 3, lg = lane >> 2;

    // stage pb/sw into smem once
    {
        int i = tid;
        pbs[i] = pb[i]; sws[i] = sw[i];
        pbs[i + 256] = pb[i + 256]; sws[i + 256] = sw[i + 256];
    }

    const int cr = tid >> 2;
    const int cc = tid & 3;
    const __nv_bfloat16* Ag = g_hsb + (size_t)m0 * NH;

    const uint32_t sbase = smem_u32(dsm);

    const int a_row = wm * 64 + (lane & 7) + ((lane >> 3) & 1) * 8;
    const int a_kb  = (lane >> 4) * 16;
    const int b_row = wn * 32 + (lane >> 4) * 8 + (lane & 7);
    const int b_kb  = ((lane >> 3) & 1) * 16;

    float part[8];
    #pragma unroll
    for (int i = 0; i < 8; i++) part[i] = 0.f;

    for (int n0i = 0; n0i < 4; n0i++) {
        const __nv_bfloat16* Bg = g_wptb + (size_t)(n0i * 128) * NH;
        float acc[4][4][4];
        #pragma unroll
        for (int mt = 0; mt < 4; mt++)
            #pragma unroll
            for (int nt = 0; nt < 4; nt++)
                #pragma unroll
                for (int q = 0; q < 4; q++) acc[mt][nt][q] = 0.f;

        // prologue: prefetch slabs 0,1 into stages 0,1
        #pragma unroll
        for (int p = 0; p < 2; p++) {
            const uint32_t aoff = sbase + p * ST_BYTES;
            const uint32_t boff = sbase + 3 * ST_BYTES + p * ST_BYTES;
            #pragma unroll
            for (int it = 0; it < 2; it++) {
                int r = cr + it * 64;
                cp16(aoff + r * 80 + cc * 16, Ag + (size_t)r * NH + p * 32 + cc * 8);
                cp16(boff + r * 80 + cc * 16, Bg + (size_t)r * NH + p * 32 + cc * 8);
            }
            asm volatile("cp.async.commit_group;");
        }

        for (int s = 0; s < 16; s++) {
            const int st = s % 3;
            if (s < 15) asm volatile("cp.async.wait_group 1;");
            else        asm volatile("cp.async.wait_group 0;");
            __syncthreads();

            if (s + 2 < 16) {
                const int pst = (s + 2) % 3;
                const int k0 = (s + 2) * 32;
                const uint32_t aoff = sbase + pst * ST_BYTES;
                const uint32_t boff = sbase + 3 * ST_BYTES + pst * ST_BYTES;
                #pragma unroll
                for (int it = 0; it < 2; it++) {
                    int r = cr + it * 64;
                    cp16(aoff + r * 80 + cc * 16, Ag + (size_t)r * NH + k0 + cc * 8);
                    cp16(boff + r * 80 + cc * 16, Bg + (size_t)r * NH + k0 + cc * 8);
                }
                asm volatile("cp.async.commit_group;");
            }

            const uint32_t abase = sbase + st * ST_BYTES + a_row * 80 + a_kb;
            const uint32_t bbase = sbase + 3 * ST_BYTES + st * ST_BYTES + b_row * 80 + b_kb;
            #pragma unroll
            for (int ks = 0; ks < 2; ks++) {
                uint32_t af[4][4], bfr[2][4];
                #pragma unroll
                for (int mt = 0; mt < 4; mt++)
                    ldsm_x4(af[mt][0], af[mt][1], af[mt][2], af[mt][3],
                            abase + mt * 16 * 80 + ks * 32);
                #pragma unroll
                for (int np = 0; np < 2; np++)
                    ldsm_x4(bfr[np][0], bfr[np][1], bfr[np][2], bfr[np][3],
                            bbase + np * 16 * 80 + ks * 32);
                #pragma unroll
                for (int mt = 0; mt < 4; mt++)
                    #pragma unroll
                    for (int nt = 0; nt < 4; nt++)
                        mma_bf16(acc[mt][nt], af[mt][0], af[mt][1], af[mt][2], af[mt][3],
                                 bfr[nt >> 1][(nt & 1) * 2], bfr[nt >> 1][(nt & 1) * 2 + 1]);
            }
        }
        __syncthreads();

        // fused epilogue: tanh.approx + dot with score weights (smem pb/sw)
        #pragma unroll
        for (int nt = 0; nt < 4; nt++) {
            int n = n0i * 128 + wn * 32 + nt * 8 + 2 * lk;
            float pv0 = pbs[n], pv1 = pbs[n + 1];
            float sv0 = sws[n], sv1 = sws[n + 1];
            #pragma unroll
            for (int mt = 0; mt < 4; mt++) {
                part[mt*2+0] += tanh_ap(acc[mt][nt][0] + pv0) * sv0
                              + tanh_ap(acc[mt][nt][1] + pv1) * sv1;
                part[mt*2+1] += tanh_ap(acc[mt][nt][2] + pv0) * sv0
                              + tanh_ap(acc[mt][nt][3] + pv1) * sv1;
            }
        }
    }
    #pragma unroll
    for (int off = 1; off < 4; off <<= 1)
        #pragma unroll
        for (int i = 0; i < 8; i++)
            part[i] += __shfl_xor_sync(0xffffffffu, part[i], off);
    if (lk == 0) {
        #pragma unroll
        for (int mt = 0; mt < 4; mt++) {
            red[wn][wm * 64 + mt * 16 + lg    ] = part[mt*2+0];
            red[wn][wm * 64 + mt * 16 + lg + 8] = part[mt*2+1];
        }
    }
    __syncthreads();
    if (tid < 128) {
        int m = m0 + tid;
        float s = red[0][tid] + red[1][tid] + red[2][tid] + red[3][tid];
        float cf = fmaxf((float)g_cnt[m], 0.f);
        g_base[m] = s + sb[0] + log1pf(cf);
    }
}

// ----------------------------------------------------------------------------
// Kernel 3: per-(b,c) masked softmax — 1024 threads, register-resident.
// ----------------------------------------------------------------------------
__global__ void __launch_bounds__(1024)
k_softmax(float* __restrict__ wout) {
    __shared__ float red[32];
    __shared__ float bcast;
    const int bc = blockIdx.x;
    const int b = bc / NC;
    const int tid = threadIdx.x;
    const int lane = tid & 31, wrp = tid >> 5;

    float4 a = *reinterpret_cast<const float4*>(&g_actT[(size_t)bc * NL + tid * 4]);
    float4 bb = *reinterpret_cast<const float4*>(&g_base[b * NL + tid * 4]);
    float v[4];
    v[0] = (a.x > 0.f) ? (bb.x + __logf(1.f + a.x)) : -INFINITY;
    v[1] = (a.y > 0.f) ? (bb.y + __logf(1.f + a.y)) : -INFINITY;
    v[2] = (a.z > 0.f) ? (bb.z + __logf(1.f + a.z)) : -INFINITY;
    v[3] = (a.w > 0.f) ? (bb.w + __logf(1.f + a.w)) : -INFINITY;

    float m = fmaxf(fmaxf(v[0], v[1]), fmaxf(v[2], v[3]));
    #pragma unroll
    for (int off = 16; off > 0; off >>= 1)
        m = fmaxf(m, __shfl_xor_sync(0xffffffffu, m, off));
    if (lane == 0) red[wrp] = m;
    __syncthreads();
    if (wrp == 0) {
        float t = red[lane];
        #pragma unroll
        for (int off = 16; off > 0; off >>= 1)
            t = fmaxf(t, __shfl_xor_sync(0xffffffffu, t, off));
        if (lane == 0) bcast = t;
    }
    __syncthreads();
    float bmax = bcast;

    float4* wrow4 = reinterpret_cast<float4*>(wout + (size_t)bc * NL);
    if (bmax == -INFINITY) {
        wrow4[tid] = make_float4(0.f, 0.f, 0.f, 0.f);
        if (tid == 0) g_hasany[bc] = 0;
        return;
    }
    float e[4];
    #pragma unroll
    for (int i = 0; i < 4; i++) {
        float d = v[i] - bmax;
        e[i] = (d < -87.f) ? 0.f : __expf(d);
    }
    float s = (e[0] + e[1]) + (e[2] + e[3]);
    #pragma unroll
    for (int off = 16; off > 0; off >>= 1)
        s += __shfl_xor_sync(0xffffffffu, s, off);
    if (lane == 0) red[wrp] = s;
    __syncthreads();
    if (wrp == 0) {
        float t = red[lane];
        #pragma unroll
        for (int off = 16; off > 0; off >>= 1)
            t += __shfl_xor_sync(0xffffffffu, t, off);
        if (lane == 0) bcast = t;
    }
    __syncthreads();
    float inv = 1.f / bcast;
    wrow4[tid] = make_float4(e[0] * inv, e[1] * inv, e[2] * inv, e[3] * inv);
    if (tid == 0) g_hasany[bc] = 1;
}

// ----------------------------------------------------------------------------
// Kernel 4: ctx partials via tf32 MMA, natural-layout tiles + 3-stage cp.async.
// (R11 config)
// ----------------------------------------------------------------------------
__global__ void __launch_bounds__(256)
k_ctx_partial(const float* __restrict__ w, const float* __restrict__ Hs) {
    __shared__ __align__(16) float As[3][64 * 20];
    __shared__ __align__(16) float Bs[3][16 * 136];
    const int h0 = blockIdx.x * 128;
    const int l0 = blockIdx.y * 512;
    const int b  = blockIdx.z;
    const int tid = threadIdx.x;
    const int wid = tid >> 5, lane = tid & 31;
    const int wm = wid & 1, wn = wid >> 1;
    const int lk = lane & 3, lg = lane >> 2;

    const uint32_t asb = smem_u32(&As[0][0]);
    const uint32_t bsb = smem_u32(&Bs[0][0]);
    const int ar = tid >> 2, ac = tid & 3;
    const float* wbase = w + (size_t)(b * NC) * NL + l0;
    const float* hbase = Hs + ((size_t)(b * NL + l0)) * NH + h0;

    float acc[2][4][4];
    #pragma unroll
    for (int mt = 0; mt < 2; mt++)
        #pragma unroll
        for (int nt = 0; nt < 4; nt++)
            #pragma unroll
            for (int q = 0; q < 4; q++) acc[mt][nt][q] = 0.f;

    #pragma unroll
    for (int p = 0; p < 2; p++) {
        cp16(asb + p * 5120 + ar * 80 + ac * 16, wbase + (size_t)ar * NL + p * 16 + ac * 4);
        #pragma unroll
        for (int i = 0; i < 2; i++) {
            int idx = tid + i * 256;
            int r = idx >> 5, ch = idx & 31;
            cp16(bsb + p * 8704 + r * 544 + ch * 16, hbase + (size_t)(p * 16 + r) * NH + ch * 4);
        }
        asm volatile("cp.async.commit_group;");
    }

    for (int s = 0; s < 32; s++) {
        const int st = s % 3;
        if (s < 31) asm volatile("cp.async.wait_group 1;");
        else        asm volatile("cp.async.wait_group 0;");
        __syncthreads();

        if (s + 2 < 32) {
            const int pst = (s + 2) % 3;
            const int k0 = (s + 2) * 16;
            cp16(asb + pst * 5120 + ar * 80 + ac * 16, wbase + (size_t)ar * NL + k0 + ac * 4);
            #pragma unroll
            for (int i = 0; i < 2; i++) {
                int idx = tid + i * 256;
                int r = idx >> 5, ch = idx & 31;
                cp16(bsb + pst * 8704 + r * 544 + ch * 16, hbase + (size_t)(k0 + r) * NH + ch * 4);
            }
            asm volatile("cp.async.commit_group;");
        }

        #pragma unroll
        for (int ks = 0; ks < 2; ks++) {
            const int kb = ks * 8;
            uint32_t af[2][4], bf[4][2];
            #pragma unroll
            for (int mt = 0; mt < 2; mt++) {
                int mb = wm * 32 + mt * 16 + lg;
                af[mt][0] = f2tf32(As[st][(mb    ) * 20 + kb + lk    ]);
                af[mt][1] = f2tf32(As[st][(mb + 8) * 20 + kb + lk    ]);
                af[mt][2] = f2tf32(As[st][(mb    ) * 20 + kb + lk + 4]);
                af[mt][3] = f2tf32(As[st][(mb + 8) * 20 + kb + lk + 4]);
            }
            #pragma unroll
            for (int nt = 0; nt < 4; nt++) {
                int nb = wn * 32 + nt * 8 + lg;
                bf[nt][0] = f2tf32(Bs[st][(kb + lk    ) * 136 + nb]);
                bf[nt][1] = f2tf32(Bs[st][(kb + lk + 4) * 136 + nb]);
            }
            #pragma unroll
            for (int mt = 0; mt < 2; mt++)
                #pragma unroll
                for (int nt = 0; nt < 4; nt++)
                    mma_tf32(acc[mt][nt], af[mt][0], af[mt][1], af[mt][2], af[mt][3],
                             bf[nt][0], bf[nt][1]);
        }
    }
    const int p = blockIdx.y;
    #pragma unroll
    for (int mt = 0; mt < 2; mt++) {
        int c0 = wm * 32 + mt * 16 + lg;
        #pragma unroll
        for (int nt = 0; nt < 4; nt++) {
            int h = h0 + wn * 32 + nt * 8 + 2 * lk;
            *reinterpret_cast<float2*>(&g_partials[p][b][c0    ][h]) =
                make_float2(acc[mt][nt][0], acc[mt][nt][1]);
            *reinterpret_cast<float2*>(&g_partials[p][b][c0 + 8][h]) =
                make_float2(acc[mt][nt][2], acc[mt][nt][3]);
        }
    }
}

// ----------------------------------------------------------------------------
// Kernel 5: finalize contexts
// ----------------------------------------------------------------------------
__global__ void k_ctx_final(const float* __restrict__ Hs) {
    int idx = blockIdx.x * 256 + threadIdx.x;
    int h = idx & (NH - 1);
    int c = (idx >> 9) & (NC - 1);
    int b = idx >> 15;
    if (g_hasany[b * NC + c]) {
        float s = 0.f;
        #pragma unroll
        for (int p = 0; p < 8; p++) s += g_partials[p][b][c][h];
        g_ctx[b][c][h] = s;
    } else {
        g_ctx[b][c][h] = Hs[((size_t)(b * NL + (NL - 1))) * NH + h];
    }
}

// ----------------------------------------------------------------------------
// Kernel 6: expanded = mix @ contexts via tf32 MMA, then gate/select.
// ----------------------------------------------------------------------------
__global__ void __launch_bounds__(256)
k_expand(const float* __restrict__ act, const float* __restrict__ Hs,
         float* __restrict__ out) {
    __shared__ float mixs[64][72];
    __shared__ float ctxs[64][72];
    __shared__ float rs[64];
    const int h0 = blockIdx.x * 64;
    const int l0 = blockIdx.y * 64;
    const int b  = blockIdx.z;
    const int tid = threadIdx.x;
    const int wid = tid >> 5, lane = tid & 31;
    const int wm = wid & 1, wn = wid >> 1;
    const int lk = lane & 3, lg = lane >> 2;

    #pragma unroll
    for (int it = 0; it < 4; it++) {
        int idx = tid + it * 256;
        int l = idx >> 4, q = idx & 15;
        float4 v = *reinterpret_cast<const float4*>(
            &act[((size_t)(b * NL + l0 + l)) * NC + q * 4]);
        mixs[q*4+0][l] = fmaxf(v.x, 0.f);
        mixs[q*4+1][l] = fmaxf(v.y, 0.f);
        mixs[q*4+2][l] = fmaxf(v.z, 0.f);
        mixs[q*4+3][l] = fmaxf(v.w, 0.f);
    }
    #pragma unroll
    for (int it = 0; it < 4; it++) {
        int idx = tid + it * 256;
        int c = idx >> 4, q = idx & 15;
        float4 v = *reinterpret_cast<const float4*>(&g_ctx[b][c][h0 + q * 4]);
        *reinterpret_cast<float4*>(&ctxs[c][q*4]) = v;
    }
    __syncthreads();
    if (tid < 64) {
        float s = 0.f;
        #pragma unroll
        for (int c = 0; c < 64; c++) s += mixs[c][tid];
        rs[tid] = 1.f / fmaxf(s, 1.f);
    }
    __syncthreads();
    #pragma unroll
    for (int it = 0; it < 16; it++) {
        int idx = tid + it * 256;
        int c = idx >> 6, l = idx & 63;
        mixs[c][l] *= rs[l];
    }
    __syncthreads();

    float acc[2][2][4];
    #pragma unroll
    for (int mt = 0; mt < 2; mt++)
        #pragma unroll
        for (int nt = 0; nt < 2; nt++)
            #pragma unroll
            for (int q = 0; q < 4; q++) acc[mt][nt][q] = 0.f;

    #pragma unroll
    for (int ks = 0; ks < 8; ks++) {
        const int kb = ks * 8;
        uint32_t af[2][4], bf[2][2];
        #pragma unroll
        for (int mt = 0; mt < 2; mt++) {
            int mb = wm * 32 + mt * 16 + lg;
            af[mt][0] = f2tf32(mixs[kb + lk    ][mb    ]);
            af[mt][1] = f2tf32(mixs[kb + lk    ][mb + 8]);
            af[mt][2] = f2tf32(mixs[kb + lk + 4][mb    ]);
            af[mt][3] = f2tf32(mixs[kb + lk + 4][mb + 8]);
        }
        #pragma unroll
        for (int nt = 0; nt < 2; nt++) {
            int nb = wn * 16 + nt * 8 + lg;
            bf[nt][0] = f2tf32(ctxs[kb + lk    ][nb]);
            bf[nt][1] = f2tf32(ctxs[kb + lk + 4][nb]);
        }
        #pragma unroll
        for (int mt = 0; mt < 2; mt++)
            #pragma unroll
            for (int nt = 0; nt < 2; nt++)
                mma_tf32(acc[mt][nt], af[mt][0], af[mt][1], af[mt][2], af[mt][3],
                         bf[nt][0], bf[nt][1]);
    }

    #pragma unroll
    for (int mt = 0; mt < 2; mt++) {
        #pragma unroll
        for (int half = 0; half < 2; half++) {
            int l = l0 + wm * 32 + mt * 16 + lg + half * 8;
            size_t m = (size_t)b * NL + l;
            bool msk = g_mask[m];
            float gate = 1.f + (float)g_cnt[m] / (float)g_maxci[b];
            #pragma unroll
            for (int nt = 0; nt < 2; nt++) {
                int h = h0 + wn * 16 + nt * 8 + 2 * lk;
                float2 o;
                if (msk) {
                    o = make_float2(acc[mt][nt][half*2+0] * gate,
                                    acc[mt][nt][half*2+1] * gate);
                } else {
                    o = *reinterpret_cast<const float2*>(&Hs[m * NH + h]);
                }
                *reinterpret_cast<float2*>(&out[m * NH + h]) = o;
            }
        }
    }
}

// ----------------------------------------------------------------------------
extern "C" void kernel_launch(void* const* d_in, const int* in_sizes, int n_in,
                              void* d_out, int out_size) {
    const float* hs = nullptr;
    const float* act = nullptr;
    const float* pw = nullptr;
    const float* sb = nullptr;
    const void*  p32k[2] = {nullptr, nullptr}; int n32 = 0;
    const float* p512[2] = {nullptr, nullptr}; int n512 = 0;
    for (int i = 0; i < n_in; i++) {
        long long s = in_sizes[i];
        if      (s == 16777216) hs  = (const float*)d_in[i];
        else if (s == 2097152)  act = (const float*)d_in[i];
        else if (s == 262144)   pw  = (const float*)d_in[i];
        else if (s == 1)        sb  = (const float*)d_in[i];
        else if (s == 32768 && n32 < 2)  p32k[n32++] = d_in[i];
        else if (s == 512   && n512 < 2) p512[n512++] = (const float*)d_in[i];
    }

    float* out = (float*)d_out;
    const size_t attended_elems = (size_t)NB * NL * NH;
    const size_t weights_elems  = (size_t)NB * NC * NL;
    float* wout;
    if ((size_t)out_size >= attended_elems + weights_elems) {
        wout = out + attended_elems;
    } else {
        cudaGetSymbolAddress((void**)&wout, g_wscratch);
    }

    cudaFuncSetAttribute(k_logits, cudaFuncAttributeMaxDynamicSharedMemorySize, LOG_SMEM);

    k_classify   <<< 1, 256 >>>((const unsigned int*)p32k[0], (const unsigned int*)p32k[1],
                                p512[0], p512[1]);
    k_prepall    <<< PREP_BLOCKS, 256 >>>(hs, act, pw, p32k[0], p32k[1]);
    k_logits     <<< NM / 128, 256, LOG_SMEM >>>(p512[0], p512[1], sb);
    k_softmax    <<< NB * NC, 1024 >>>(wout);
    k_ctx_partial<<< dim3(NH / 128, 8, NB), 256 >>>(wout, hs);
    k_ctx_final  <<< (NB * NC * NH) / 256, 256 >>>(hs);
    k_expand     <<< dim3(NH / 64, NL / 64, NB), 256 >>>(act, hs, out);
}

// round 14
// speedup vs baseline: 1.0687x; 1.0008x over previous
#include <cuda_runtime.h>
#include <cuda_bf16.h>
#include <math.h>
#include <stdint.h>

#define NB 8
#define NL 4096
#define NH 512
#define NC 64
#define NA 512
#define NM (NB*NL)

// scratch (no allocations allowed -> __device__ globals)
__device__ int   g_sel;
__device__ int   g_cnt[NM];
__device__ unsigned char g_mask[NM];
__device__ int   g_maxci[NB];
__device__ float g_base[NM];
__device__ float g_base2[2][NM];                                 // N-split logit partials
__device__ float g_partials[8][NB][NC][NH];
__device__ float g_ctx[NB][NC][NH];
__device__ int   g_hasany[NB*NC];
__device__ float g_wscratch[(size_t)NB*NC*NL];
__device__ float g_actT[(size_t)NB*NC*NL];                       // activity transposed [b][c][l]
__device__ __align__(16) __nv_bfloat16 g_wptb[(size_t)NA*NH];    // W transposed bf16 [n][k]
__device__ __align__(16) __nv_bfloat16 g_hsb[(size_t)NM*NH];     // hidden bf16 [m][k]

__device__ __forceinline__ uint32_t f2tf32(float x) {
    uint32_t r; asm("cvt.rna.tf32.f32 %0, %1;" : "=r"(r) : "f"(x)); return r;
}
__device__ __forceinline__ uint32_t pk2(float lo, float hi) {
    uint32_t r; asm("cvt.rn.bf16x2.f32 %0, %1, %2;" : "=r"(r) : "f"(hi), "f"(lo)); return r;
}
__device__ __forceinline__ float tanh_ap(float x) {
    float y; asm("tanh.approx.f32 %0, %1;" : "=f"(y) : "f"(x)); return y;
}
__device__ __forceinline__ void mma_tf32(float c[4], uint32_t a0, uint32_t a1,
                                         uint32_t a2, uint32_t a3,
                                         uint32_t b0, uint32_t b1) {
    asm volatile("mma.sync.aligned.m16n8k8.row.col.f32.tf32.tf32.f32 "
                 "{%0,%1,%2,%3}, {%4,%5,%6,%7}, {%8,%9}, {%0,%1,%2,%3};\n"
                 : "+f"(c[0]), "+f"(c[1]), "+f"(c[2]), "+f"(c[3])
                 : "r"(a0), "r"(a1), "r"(a2), "r"(a3), "r"(b0), "r"(b1));
}
__device__ __forceinline__ void mma_bf16(float c[4], uint32_t a0, uint32_t a1,
                                         uint32_t a2, uint32_t a3,
                                         uint32_t b0, uint32_t b1) {
    asm volatile("mma.sync.aligned.m16n8k16.row.col.f32.bf16.bf16.f32 "
                 "{%0,%1,%2,%3}, {%4,%5,%6,%7}, {%8,%9}, {%0,%1,%2,%3};\n"
                 : "+f"(c[0]), "+f"(c[1]), "+f"(c[2]), "+f"(c[3])
                 : "r"(a0), "r"(a1), "r"(a2), "r"(a3), "r"(b0), "r"(b1));
}
__device__ __forceinline__ void ldsm_x4(uint32_t& r0, uint32_t& r1, uint32_t& r2,
                                        uint32_t& r3, uint32_t addr) {
    asm volatile("ldmatrix.sync.aligned.m8n8.x4.shared.b16 {%0,%1,%2,%3}, [%4];"
                 : "=r"(r0), "=r"(r1), "=r"(r2), "=r"(r3) : "r"(addr));
}
__device__ __forceinline__ void cp16(uint32_t dst, const void* src) {
    asm volatile("cp.async.cg.shared.global [%0], [%1], 16;" :: "r"(dst), "l"(src));
}
__device__ __forceinline__ uint32_t smem_u32(const void* p) {
    uint32_t a;
    asm("{ .reg .u64 t; cvta.to.shared.u64 t, %1; cvt.u32.u64 %0, t; }" : "=r"(a) : "l"(p));
    return a;
}

// ----------------------------------------------------------------------------
// Kernel 0: classify ambiguous input pairs + init maxci.
// ----------------------------------------------------------------------------
__global__ void k_classify(const unsigned int* __restrict__ a, const unsigned int* __restrict__ b,
                           const float* __restrict__ f0, const float* __restrict__ f1) {
    __shared__ unsigned int ra[256], rb[256];
    __shared__ float fa[256];
    const int tid = threadIdx.x;
    if (tid < NB) g_maxci[tid] = 1;
    unsigned int ma = 0, mb = 0;
    for (int i = tid; i < 8192; i += 256) {
        ma = max(ma, a[i]);
        mb = max(mb, b[i]);
    }
    float f0m = 0.f;
    for (int i = tid; i < 512; i += 256) f0m = fmaxf(f0m, fabsf(f0[i]));
    (void)f1;
    ra[tid] = ma; rb[tid] = mb; fa[tid] = f0m;
    __syncthreads();
    for (int s = 128; s > 0; s >>= 1) {
        if (tid < s) {
            ra[tid] = max(ra[tid], ra[tid + s]);
            rb[tid] = max(rb[tid], rb[tid + s]);
            fa[tid] = fmaxf(fa[tid], fa[tid + s]);
        }
        __syncthreads();
    }
    if (tid == 0) {
        int sel = 0;
        bool a_is_count = (ra[0] >= 2u && ra[0] < 64u);
        if (a_is_count) sel |= 1;
        unsigned int mmax = a_is_count ? rb[0] : ra[0];
        if (mmax >= 256u) sel |= 2;
        if (fa[0] < 1e-30f) sel |= 4;
        g_sel = sel;
    }
}

// ----------------------------------------------------------------------------
// Kernel 0f: FUSED preprocessing (cvth / acttr / cvtw / prep by block range)
// ----------------------------------------------------------------------------
#define PREP_BLOCKS 10496
__global__ void k_prepall(const float* __restrict__ Hs, const float* __restrict__ act,
                          const float* __restrict__ Wp,
                          const void* __restrict__ c0, const void* __restrict__ c1) {
    __shared__ float t[32][33];
    __shared__ int sm[256];
    const int tid = threadIdx.x;
    int bid = blockIdx.x;

    if (bid < 8192) {                       // ---- cvth ----
        size_t i = ((size_t)bid * 256 + tid) * 8;
        float4 a = *reinterpret_cast<const float4*>(&Hs[i]);
        float4 b = *reinterpret_cast<const float4*>(&Hs[i + 4]);
        uint4 u;
        u.x = pk2(a.x, a.y); u.y = pk2(a.z, a.w);
        u.z = pk2(b.x, b.y); u.w = pk2(b.z, b.w);
        *reinterpret_cast<uint4*>(&g_hsb[i]) = u;
        return;
    }
    bid -= 8192;
    if (bid < 2048) {                       // ---- acttr ----
        const int l0 = (bid & 127) * 32;
        const int c0i = ((bid >> 7) & 1) * 32;
        const int b  = bid >> 8;
        const int x = tid & 31, y = tid >> 5;   // 32 x 8
        #pragma unroll
        for (int i = y; i < 32; i += 8)
            t[i][x] = act[((size_t)(b * NL + l0 + i)) * NC + c0i + x];
        __syncthreads();
        #pragma unroll
        for (int i = y; i < 32; i += 8)
            g_actT[((size_t)(b * NC + c0i + i)) * NL + l0 + x] = t[x][i];
        return;
    }
    bid -= 2048;
    if (bid < 128) {                        // ---- cvtw ----
        const int idx = bid * 256 + tid;
        const int n = idx & 511;
        const int k0 = (idx >> 9) * 8;
        float v[8];
        #pragma unroll
        for (int j = 0; j < 8; j++) v[j] = Wp[(size_t)(k0 + j) * NA + n];
        uint4 u;
        u.x = pk2(v[0], v[1]); u.y = pk2(v[2], v[3]);
        u.z = pk2(v[4], v[5]); u.w = pk2(v[6], v[7]);
        *reinterpret_cast<uint4*>(&g_wptb[(size_t)n * NH + k0]) = u;
        return;
    }
    bid -= 128;
    {                                       // ---- prep ---- (128 blocks)
        const int i = bid * 256 + tid;
        const int sel = g_sel;
        const int* cntp   = (const int*)((sel & 1) ? c0 : c1);
        const void* maskp = (sel & 1) ? c1 : c0;
        int cv = cntp[i];
        g_cnt[i] = cv;
        unsigned char mv;
        if (sel & 2) mv = (((const unsigned char*)maskp)[i] != 0) ? 1 : 0;
        else         mv = (((const int*)maskp)[i] != 0) ? 1 : 0;
        g_mask[i] = mv;
        sm[tid] = cv; __syncthreads();
        for (int s = 128; s > 0; s >>= 1) {
            if (tid < s) sm[tid] = max(sm[tid], sm[tid + s]);
            __syncthreads();
        }
        if (tid == 0) atomicMax(&g_maxci[bid >> 4], sm[0]);
    }
}

// ----------------------------------------------------------------------------
// Kernel 1: fused logits, N-split by 2 for load balance.
// grid (NM/128, 2); blockIdx.y selects n-half. 3-stage cp.async, bf16 mma.sync.
// ----------------------------------------------------------------------------
#define ST_BYTES 10240
#define LOG_SMEM (6 * ST_BYTES)

__global__ void __launch_bounds__(256, 2)
k_logits(const float* __restrict__ v0, const float* __restrict__ v1) {
    extern __shared__ __align__(16) char dsm[];
    __shared__ float red[4][128];
    __shared__ float pbs[256], sws[256];
    const int sel = g_sel;
    const float* pb = (sel & 4) ? v0 : v1;
    const float* sw = (sel & 4) ? v1 : v0;
    const int m0  = blockIdx.x * 128;
    const int nh  = blockIdx.y;             // n-half: 0 or 1
    const int tid = threadIdx.x;
    const int wid = tid >> 5, lane = tid & 31;
    const int wm = wid & 1, wn = wid >> 1;
    const int lk = lane & 3, lg = lane >> 2;

    // stage this half's pb/sw into smem
    pbs[tid] = pb[nh * 256 + tid];
    sws[tid] = sw[nh * 256 + tid];

    const int cr = tid >> 2;
    const int cc = tid & 3;
    const __nv_bfloat16* Ag = g_hsb + (size_t)m0 * NH;

    const uint32_t sbase = smem_u32(dsm);

    const int a_row = wm * 64 + (lane & 7) + ((lane >> 3) & 1) * 8;
    const int a_kb  = (lane >> 4) * 16;
    const int b_row = wn * 32 + (lane >> 4) * 8 + (lane & 7);
    const int b_kb  = ((lane >> 3) & 1) * 16;

    float part[8];
    #pragma unroll
    for (int i = 0; i < 8; i++) part[i] = 0.f;

    for (int ch = 0; ch < 2; ch++) {
        const int n0i = nh * 2 + ch;
        const __nv_bfloat16* Bg = g_wptb + (size_t)(n0i * 128) * NH;
        float acc[4][4][4];
        #pragma unroll
        for (int mt = 0; mt < 4; mt++)
            #pragma unroll
            for (int nt = 0; nt < 4; nt++)
                #pragma unroll
                for (int q = 0; q < 4; q++) acc[mt][nt][q] = 0.f;

        // prologue: prefetch slabs 0,1 into stages 0,1
        #pragma unroll
        for (int p = 0; p < 2; p++) {
            const uint32_t aoff = sbase + p * ST_BYTES;
            const uint32_t boff = sbase + 3 * ST_BYTES + p * ST_BYTES;
            #pragma unroll
            for (int it = 0; it < 2; it++) {
                int r = cr + it * 64;
                cp16(aoff + r * 80 + cc * 16, Ag + (size_t)r * NH + p * 32 + cc * 8);
                cp16(boff + r * 80 + cc * 16, Bg + (size_t)r * NH + p * 32 + cc * 8);
            }
            asm volatile("cp.async.commit_group;");
        }

        for (int s = 0; s < 16; s++) {
            const int st = s % 3;
            if (s < 15) asm volatile("cp.async.wait_group 1;");
            else        asm volatile("cp.async.wait_group 0;");
            __syncthreads();

            if (s + 2 < 16) {
                const int pst = (s + 2) % 3;
                const int k0 = (s + 2) * 32;
                const uint32_t aoff = sbase + pst * ST_BYTES;
                const uint32_t boff = sbase + 3 * ST_BYTES + pst * ST_BYTES;
                #pragma unroll
                for (int it = 0; it < 2; it++) {
                    int r = cr + it * 64;
                    cp16(aoff + r * 80 + cc * 16, Ag + (size_t)r * NH + k0 + cc * 8);
                    cp16(boff + r * 80 + cc * 16, Bg + (size_t)r * NH + k0 + cc * 8);
                }
                asm volatile("cp.async.commit_group;");
            }

            const uint32_t abase = sbase + st * ST_BYTES + a_row * 80 + a_kb;
            const uint32_t bbase = sbase + 3 * ST_BYTES + st * ST_BYTES + b_row * 80 + b_kb;
            #pragma unroll
            for (int ks = 0; ks < 2; ks++) {
                uint32_t af[4][4], bfr[2][4];
                #pragma unroll
                for (int mt = 0; mt < 4; mt++)
                    ldsm_x4(af[mt][0], af[mt][1], af[mt][2], af[mt][3],
                            abase + mt * 16 * 80 + ks * 32);
                #pragma unroll
                for (int np = 0; np < 2; np++)
                    ldsm_x4(bfr[np][0], bfr[np][1], bfr[np][2], bfr[np][3],
                            bbase + np * 16 * 80 + ks * 32);
                #pragma unroll
                for (int mt = 0; mt < 4; mt++)
                    #pragma unroll
                    for (int nt = 0; nt < 4; nt++)
                        mma_bf16(acc[mt][nt], af[mt][0], af[mt][1], af[mt][2], af[mt][3],
                                 bfr[nt >> 1][(nt & 1) * 2], bfr[nt >> 1][(nt & 1) * 2 + 1]);
            }
        }
        __syncthreads();

        // fused epilogue: tanh.approx + dot with score weights (smem pb/sw)
        #pragma unroll
        for (int nt = 0; nt < 4; nt++) {
            int n = ch * 128 + wn * 32 + nt * 8 + 2 * lk;   // within this half
            float pv0 = pbs[n], pv1 = pbs[n + 1];
            float sv0 = sws[n], sv1 = sws[n + 1];
            #pragma unroll
            for (int mt = 0; mt < 4; mt++) {
                part[mt*2+0] += tanh_ap(acc[mt][nt][0] + pv0) * sv0
                              + tanh_ap(acc[mt][nt][1] + pv1) * sv1;
                part[mt*2+1] += tanh_ap(acc[mt][nt][2] + pv0) * sv0
                              + tanh_ap(acc[mt][nt][3] + pv1) * sv1;
            }
        }
    }
    #pragma unroll
    for (int off = 1; off < 4; off <<= 1)
        #pragma unroll
        for (int i = 0; i < 8; i++)
            part[i] += __shfl_xor_sync(0xffffffffu, part[i], off);
    if (lk == 0) {
        #pragma unroll
        for (int mt = 0; mt < 4; mt++) {
            red[wn][wm * 64 + mt * 16 + lg    ] = part[mt*2+0];
            red[wn][wm * 64 + mt * 16 + lg + 8] = part[mt*2+1];
        }
    }
    __syncthreads();
    if (tid < 128) {
        int m = m0 + tid;
        g_base2[nh][m] = red[0][tid] + red[1][tid] + red[2][tid] + red[3][tid];
    }
}

// ----------------------------------------------------------------------------
// Kernel 1b: combine N-split logit partials + bias + log1p(count)
// ----------------------------------------------------------------------------
__global__ void k_basefin(const float* __restrict__ sb) {
    const int m = blockIdx.x * 256 + threadIdx.x;
    float cf = fmaxf((float)g_cnt[m], 0.f);
    g_base[m] = g_base2[0][m] + g_base2[1][m] + sb[0] + log1pf(cf);
}

// ----------------------------------------------------------------------------
// Kernel 3: per-(b,c) masked softmax — 1024 threads, register-resident.
// ----------------------------------------------------------------------------
__global__ void __launch_bounds__(1024)
k_softmax(float* __restrict__ wout) {
    __shared__ float red[32];
    __shared__ float bcast;
    const int bc = blockIdx.x;
    const int b = bc / NC;
    const int tid = threadIdx.x;
    const int lane = tid & 31, wrp = tid >> 5;

    float4 a = *reinterpret_cast<const float4*>(&g_actT[(size_t)bc * NL + tid * 4]);
    float4 bb = *reinterpret_cast<const float4*>(&g_base[b * NL + tid * 4]);
    float v[4];
    v[0] = (a.x > 0.f) ? (bb.x + __logf(1.f + a.x)) : -INFINITY;
    v[1] = (a.y > 0.f) ? (bb.y + __logf(1.f + a.y)) : -INFINITY;
    v[2] = (a.z > 0.f) ? (bb.z + __logf(1.f + a.z)) : -INFINITY;
    v[3] = (a.w > 0.f) ? (bb.w + __logf(1.f + a.w)) : -INFINITY;

    float m = fmaxf(fmaxf(v[0], v[1]), fmaxf(v[2], v[3]));
    #pragma unroll
    for (int off = 16; off > 0; off >>= 1)
        m = fmaxf(m, __shfl_xor_sync(0xffffffffu, m, off));
    if (lane == 0) red[wrp] = m;
    __syncthreads();
    if (wrp == 0) {
        float t = red[lane];
        #pragma unroll
        for (int off = 16; off > 0; off >>= 1)
            t = fmaxf(t, __shfl_xor_sync(0xffffffffu, t, off));
        if (lane == 0) bcast = t;
    }
    __syncthreads();
    float bmax = bcast;

    float4* wrow4 = reinterpret_cast<float4*>(wout + (size_t)bc * NL);
    if (bmax == -INFINITY) {
        wrow4[tid] = make_float4(0.f, 0.f, 0.f, 0.f);
        if (tid == 0) g_hasany[bc] = 0;
        return;
    }
    float e[4];
    #pragma unroll
    for (int i = 0; i < 4; i++) {
        float d = v[i] - bmax;
        e[i] = (d < -87.f) ? 0.f : __expf(d);
    }
    float s = (e[0] + e[1]) + (e[2] + e[3]);
    #pragma unroll
    for (int off = 16; off > 0; off >>= 1)
        s += __shfl_xor_sync(0xffffffffu, s, off);
    if (lane == 0) red[wrp] = s;
    __syncthreads();
    if (wrp == 0) {
        float t = red[lane];
        #pragma unroll
        for (int off = 16; off > 0; off >>= 1)
            t += __shfl_xor_sync(0xffffffffu, t, off);
        if (lane == 0) bcast = t;
    }
    __syncthreads();
    float inv = 1.f / bcast;
    wrow4[tid] = make_float4(e[0] * inv, e[1] * inv, e[2] * inv, e[3] * inv);
    if (tid == 0) g_hasany[bc] = 1;
}

// ----------------------------------------------------------------------------
// Kernel 4: ctx partials via tf32 MMA, natural-layout tiles + 3-stage cp.async.
// ----------------------------------------------------------------------------
__global__ void __launch_bounds__(256)
k_ctx_partial(const float* __restrict__ w, const float* __restrict__ Hs) {
    __shared__ __align__(16) float As[3][64 * 20];
    __shared__ __align__(16) float Bs[3][16 * 136];
    const int h0 = blockIdx.x * 128;
    const int l0 = blockIdx.y * 512;
    const int b  = blockIdx.z;
    const int tid = threadIdx.x;
    const int wid = tid >> 5, lane = tid & 31;
    const int wm = wid & 1, wn = wid >> 1;
    const int lk = lane & 3, lg = lane >> 2;

    const uint32_t asb = smem_u32(&As[0][0]);
    const uint32_t bsb = smem_u32(&Bs[0][0]);
    const int ar = tid >> 2, ac = tid & 3;
    const float* wbase = w + (size_t)(b * NC) * NL + l0;
    const float* hbase = Hs + ((size_t)(b * NL + l0)) * NH + h0;

    float acc[2][4][4];
    #pragma unroll
    for (int mt = 0; mt < 2; mt++)
        #pragma unroll
        for (int nt = 0; nt < 4; nt++)
            #pragma unroll
            for (int q = 0; q < 4; q++) acc[mt][nt][q] = 0.f;

    #pragma unroll
    for (int p = 0; p < 2; p++) {
        cp16(asb + p * 5120 + ar * 80 + ac * 16, wbase + (size_t)ar * NL + p * 16 + ac * 4);
        #pragma unroll
        for (int i = 0; i < 2; i++) {
            int idx = tid + i * 256;
            int r = idx >> 5, ch = idx & 31;
            cp16(bsb + p * 8704 + r * 544 + ch * 16, hbase + (size_t)(p * 16 + r) * NH + ch * 4);
        }
        asm volatile("cp.async.commit_group;");
    }

    for (int s = 0; s < 32; s++) {
        const int st = s % 3;
        if (s < 31) asm volatile("cp.async.wait_group 1;");
        else        asm volatile("cp.async.wait_group 0;");
        __syncthreads();

        if (s + 2 < 32) {
            const int pst = (s + 2) % 3;
            const int k0 = (s + 2) * 16;
            cp16(asb + pst * 5120 + ar * 80 + ac * 16, wbase + (size_t)ar * NL + k0 + ac * 4);
            #pragma unroll
            for (int i = 0; i < 2; i++) {
                int idx = tid + i * 256;
                int r = idx >> 5, ch = idx & 31;
                cp16(bsb + pst * 8704 + r * 544 + ch * 16, hbase + (size_t)(k0 + r) * NH + ch * 4);
            }
            asm volatile("cp.async.commit_group;");
        }

        #pragma unroll
        for (int ks = 0; ks < 2; ks++) {
            const int kb = ks * 8;
            uint32_t af[2][4], bf[4][2];
            #pragma unroll
            for (int mt = 0; mt < 2; mt++) {
                int mb = wm * 32 + mt * 16 + lg;
                af[mt][0] = f2tf32(As[st][(mb    ) * 20 + kb + lk    ]);
                af[mt][1] = f2tf32(As[st][(mb + 8) * 20 + kb + lk    ]);
                af[mt][2] = f2tf32(As[st][(mb    ) * 20 + kb + lk + 4]);
                af[mt][3] = f2tf32(As[st][(mb + 8) * 20 + kb + lk + 4]);
            }
            #pragma unroll
            for (int nt = 0; nt < 4; nt++) {
                int nb = wn * 32 + nt * 8 + lg;
                bf[nt][0] = f2tf32(Bs[st][(kb + lk    ) * 136 + nb]);
                bf[nt][1] = f2tf32(Bs[st][(kb + lk + 4) * 136 + nb]);
            }
            #pragma unroll
            for (int mt = 0; mt < 2; mt++)
                #pragma unroll
                for (int nt = 0; nt < 4; nt++)
                    mma_tf32(acc[mt][nt], af[mt][0], af[mt][1], af[mt][2], af[mt][3],
                             bf[nt][0], bf[nt][1]);
        }
    }
    const int p = blockIdx.y;
    #pragma unroll
    for (int mt = 0; mt < 2; mt++) {
        int c0 = wm * 32 + mt * 16 + lg;
        #pragma unroll
        for (int nt = 0; nt < 4; nt++) {
            int h = h0 + wn * 32 + nt * 8 + 2 * lk;
            *reinterpret_cast<float2*>(&g_partials[p][b][c0    ][h]) =
                make_float2(acc[mt][nt][0], acc[mt][nt][1]);
            *reinterpret_cast<float2*>(&g_partials[p][b][c0 + 8][h]) =
                make_float2(acc[mt][nt][2], acc[mt][nt][3]);
        }
    }
}

// ----------------------------------------------------------------------------
// Kernel 5: finalize contexts
// ----------------------------------------------------------------------------
__global__ void k_ctx_final(const float* __restrict__ Hs) {
    int idx = blockIdx.x * 256 + threadIdx.x;
    int h = idx & (NH - 1);
    int c = (idx >> 9) & (NC - 1);
    int b = idx >> 15;
    if (g_hasany[b * NC + c]) {
        float s = 0.f;
        #pragma unroll
        for (int p = 0; p < 8; p++) s += g_partials[p][b][c][h];
        g_ctx[b][c][h] = s;
    } else {
        g_ctx[b][c][h] = Hs[((size_t)(b * NL + (NL - 1))) * NH + h];
    }
}

// ----------------------------------------------------------------------------
// Kernel 6: expanded = mix @ contexts via tf32 MMA, then gate/select.
// ----------------------------------------------------------------------------
__global__ void __launch_bounds__(256)
k_expand(const float* __restrict__ act, const float* __restrict__ Hs,
         float* __restrict__ out) {
    __shared__ float mixs[64][72];
    __shared__ float ctxs[64][72];
    __shared__ float rs[64];
    const int h0 = blockIdx.x * 64;
    const int l0 = blockIdx.y * 64;
    const int b  = blockIdx.z;
    const int tid = threadIdx.x;
    const int wid = tid >> 5, lane = tid & 31;
    const int wm = wid & 1, wn = wid >> 1;
    const int lk = lane & 3, lg = lane >> 2;

    #pragma unroll
    for (int it = 0; it < 4; it++) {
        int idx = tid + it * 256;
        int l = idx >> 4, q = idx & 15;
        float4 v = *reinterpret_cast<const float4*>(
            &act[((size_t)(b * NL + l0 + l)) * NC + q * 4]);
        mixs[q*4+0][l] = fmaxf(v.x, 0.f);
        mixs[q*4+1][l] = fmaxf(v.y, 0.f);
        mixs[q*4+2][l] = fmaxf(v.z, 0.f);
        mixs[q*4+3][l] = fmaxf(v.w, 0.f);
    }
    #pragma unroll
    for (int it = 0; it < 4; it++) {
        int idx = tid + it * 256;
        int c = idx >> 4, q = idx & 15;
        float4 v = *reinterpret_cast<const float4*>(&g_ctx[b][c][h0 + q * 4]);
        *reinterpret_cast<float4*>(&ctxs[c][q*4]) = v;
    }
    __syncthreads();
    if (tid < 64) {
        float s = 0.f;
        #pragma unroll
        for (int c = 0; c < 64; c++) s += mixs[c][tid];
        rs[tid] = 1.f / fmaxf(s, 1.f);
    }
    __syncthreads();
    #pragma unroll
    for (int it = 0; it < 16; it++) {
        int idx = tid + it * 256;
        int c = idx >> 6, l = idx & 63;
        mixs[c][l] *= rs[l];
    }
    __syncthreads();

    float acc[2][2][4];
    #pragma unroll
    for (int mt = 0; mt < 2; mt++)
        #pragma unroll
        for (int nt = 0; nt < 2; nt++)
            #pragma unroll
            for (int q = 0; q < 4; q++) acc[mt][nt][q] = 0.f;

    #pragma unroll
    for (int ks = 0; ks < 8; ks++) {
        const int kb = ks * 8;
        uint32_t af[2][4], bf[2][2];
        #pragma unroll
        for (int mt = 0; mt < 2; mt++) {
            int mb = wm * 32 + mt * 16 + lg;
            af[mt][0] = f2tf32(mixs[kb + lk    ][mb    ]);
            af[mt][1] = f2tf32(mixs[kb + lk    ][mb + 8]);
            af[mt][2] = f2tf32(mixs[kb + lk + 4][mb    ]);
            af[mt][3] = f2tf32(mixs[kb + lk + 4][mb + 8]);
        }
        #pragma unroll
        for (int nt = 0; nt < 2; nt++) {
            int nb = wn * 16 + nt * 8 + lg;
            bf[nt][0] = f2tf32(ctxs[kb + lk    ][nb]);
            bf[nt][1] = f2tf32(ctxs[kb + lk + 4][nb]);
        }
        #pragma unroll
        for (int mt = 0; mt < 2; mt++)
            #pragma unroll
            for (int nt = 0; nt < 2; nt++)
                mma_tf32(acc[mt][nt], af[mt][0], af[mt][1], af[mt][2], af[mt][3],
                         bf[nt][0], bf[nt][1]);
    }

    #pragma unroll
    for (int mt = 0; mt < 2; mt++) {
        #pragma unroll
        for (int half = 0; half < 2; half++) {
            int l = l0 + wm * 32 + mt * 16 + lg + half * 8;
            size_t m = (size_t)b * NL + l;
            bool msk = g_mask[m];
            float gate = 1.f + (float)g_cnt[m] / (float)g_maxci[b];
            #pragma unroll
            for (int nt = 0; nt < 2; nt++) {
                int h = h0 + wn * 16 + nt * 8 + 2 * lk;
                float2 o;
                if (msk) {
                    o = make_float2(acc[mt][nt][half*2+0] * gate,
                                    acc[mt][nt][half*2+1] * gate);
                } else {
                    o = *reinterpret_cast<const float2*>(&Hs[m * NH + h]);
                }
                *reinterpret_cast<float2*>(&out[m * NH + h]) = o;
            }
        }
    }
}

// ----------------------------------------------------------------------------
extern "C" void kernel_launch(void* const* d_in, const int* in_sizes, int n_in,
                              void* d_out, int out_size) {
    const float* hs = nullptr;
    const float* act = nullptr;
    const float* pw = nullptr;
    const float* sb = nullptr;
    const void*  p32k[2] = {nullptr, nullptr}; int n32 = 0;
    const float* p512[2] = {nullptr, nullptr}; int n512 = 0;
    for (int i = 0; i < n_in; i++) {
        long long s = in_sizes[i];
        if      (s == 16777216) hs  = (const float*)d_in[i];
        else if (s == 2097152)  act = (const float*)d_in[i];
        else if (s == 262144)   pw  = (const float*)d_in[i];
        else if (s == 1)        sb  = (const float*)d_in[i];
        else if (s == 32768 && n32 < 2)  p32k[n32++] = d_in[i];
        else if (s == 512   && n512 < 2) p512[n512++] = (const float*)d_in[i];
    }

    float* out = (float*)d_out;
    const size_t attended_elems = (size_t)NB * NL * NH;
    const size_t weights_elems  = (size_t)NB * NC * NL;
    float* wout;
    if ((size_t)out_size >= attended_elems + weights_elems) {
        wout = out + attended_elems;
    } else {
        cudaGetSymbolAddress((void**)&wout, g_wscratch);
    }

    cudaFuncSetAttribute(k_logits, cudaFuncAttributeMaxDynamicSharedMemorySize, LOG_SMEM);

    k_classify   <<< 1, 256 >>>((const unsigned int*)p32k[0], (const unsigned int*)p32k[1],
                                p512[0], p512[1]);
    k_prepall    <<< PREP_BLOCKS, 256 >>>(hs, act, pw, p32k[0], p32k[1]);
    k_logits     <<< dim3(NM / 128, 2), 256, LOG_SMEM >>>(p512[0], p512[1]);
    k_basefin    <<< NM / 256, 256 >>>(sb);
    k_softmax    <<< NB * NC, 1024 >>>(wout);
    k_ctx_partial<<< dim3(NH / 128, 8, NB), 256 >>>(wout, hs);
    k_ctx_final  <<< (NB * NC * NH) / 256, 256 >>>(hs);
    k_expand     <<< dim3(NH / 64, NL / 64, NB), 256 >>>(act, hs, out);
}